// round 16
// baseline (speedup 1.0000x reference)
#include <cuda_runtime.h>
#include <cstdint>
#include <cstddef>

// ---------------------------------------------------------------------------
// WaveNet gated residual block, tf32 mma.sync (sm_103 baseline PTX).
//
// R14 = R13 with 128-thread CTAs and 64x64 warp tiles (2M x 2N) at occ 2.
//   Per-kc smem traffic/SM drops 256KB -> 192KB (< tensor 2048 cyc), removing
//   the crossbar co-bottleneck identified from the R13 model.
//   gate_kernel: tiles M128 x N128 (interleaved tanh|sig rows -> 64 channels),
//                epilogue m -> gmem mscratch at PLAIN channel positions.
//   out_kernel : tiles M128 x N128 over [res | skip0 | skip1], A = mscratch.
// Both: 4 warps, warp tile 64x64 (acc 128/thread; 128-thr CTA at occ 2 has a
// 256-reg budget), ldmatrix A-fragments, LDS.64 q-packed B-fragments,
// 3-stage cp.async ring, one __syncthreads per k32 chunk.
// ---------------------------------------------------------------------------

#define DEVFN __device__ __forceinline__

// smem float offsets (per kernel): A stages 3x4096, B stages 3x4096
static constexpr int AOFF = 0;
static constexpr int BOFF = 12288;
static constexpr int SMEM_BYTES = 24576 * 4;   // 98304 -> 2 CTAs/SM

__device__ float wscratch[896 * 256];        // packed tf32 weights (896 KB)
__device__ float xscratch[131072 * 128];     // tf32-rounded plain x (64 MB)
__device__ float mscratch[(size_t)131072 * 256];  // gated activations m (128 MB)

// ------------------------------- helpers -----------------------------------
DEVFN uint32_t smaddr(const void* p) {
    uint32_t a;
    asm("{ .reg .u64 t; cvta.to.shared.u64 t, %1; cvt.u32.u64 %0, t; }" : "=r"(a) : "l"(p));
    return a;
}
DEVFN uint32_t tf32r(float x) { uint32_t u; asm("cvt.rna.tf32.f32 %0, %1;" : "=r"(u) : "f"(x)); return u; }
DEVFN float ex2f(float x) { float y; asm("ex2.approx.ftz.f32 %0, %1;" : "=f"(y) : "f"(x)); return y; }
DEVFN float rcpf(float x) { float y; asm("rcp.approx.ftz.f32 %0, %1;" : "=f"(y) : "f"(x)); return y; }

// tanh(a)*sigmoid(b) = (u-1)*v/((u+1)(v+1)), u=e^{2a}, v=e^{b}; clamped.
DEVFN float gatem(float a, float b) {
    a = fminf(fmaxf(a, -15.f), 15.f);
    b = fminf(fmaxf(b, -30.f), 30.f);
    float u = ex2f(a * 2.8853900817779268f);
    float v = ex2f(b * 1.4426950408889634f);
    float m = (u - 1.f) * v * rcpf((u + 1.f) * (v + 1.f));
    return __uint_as_float(tf32r(m));
}

DEVFN void cpa16(uint32_t dst, const void* src, int sz) {
    asm volatile("cp.async.cg.shared.global [%0], [%1], 16, %2;"
                 :: "r"(dst), "l"(src), "r"(sz) : "memory");
}
DEVFN void cpcommit() { asm volatile("cp.async.commit_group;" ::: "memory"); }
#define CPWAIT(n) asm volatile("cp.async.wait_group %0;" :: "n"(n) : "memory")

// m16n8k8 tf32 mma, row.col, f32 accum
DEVFN void mma8(float* d, const uint32_t* a, const uint32_t* b) {
    asm("mma.sync.aligned.m16n8k8.row.col.f32.tf32.tf32.f32 "
        "{%0,%1,%2,%3}, {%4,%5,%6,%7}, {%8,%9}, {%0,%1,%2,%3};"
        : "+f"(d[0]), "+f"(d[1]), "+f"(d[2]), "+f"(d[3])
        : "r"(a[0]), "r"(a[1]), "r"(a[2]), "r"(a[3]), "r"(b[0]), "r"(b[1]));
}

// ldmatrix x4: one full 16x8 tf32 A-fragment (b16 view, reg = one tf32)
DEVFN void ldsm4(uint32_t* r, uint32_t addr) {
    asm volatile("ldmatrix.sync.aligned.m8n8.x4.shared.b16 {%0,%1,%2,%3}, [%4];"
                 : "=r"(r[0]), "=r"(r[1]), "=r"(r[2]), "=r"(r[3]) : "r"(addr));
}

// ------------------------------ prep kernel --------------------------------
// wscratch rows (256 q-packed floats each, q(k)=(k&~7)+((k&3)<<1)+((k>>2)&1)):
//   0..511   gate: row = p*256 + t; G=t>>4, is_sig=(t>>3)&1, e=t&7,
//            channel C = p*128 + G*8 + (e>>1) + (e&1)*4  (pairing permutation)
//   512..767 out: res 0..127 | skip 0..127
//   768..895 out: skip 128..255
// xscratch: 128 PLAIN tf32 floats per token.
__global__ void __launch_bounds__(256)
prep_kernel(const float* __restrict__ wt, const float* __restrict__ ws,
            const float* __restrict__ wr, const float* __restrict__ wk,
            const float* __restrict__ x) {
    int bid = blockIdx.x, tid = threadIdx.x;
    if (bid < 896) {
        int idx = bid * 256 + tid;
        int row = idx >> 8, k = idx & 255;
        float v;
        if (row < 512) {
            int p = row >> 8, t = row & 255;
            int G = t >> 4, is_sig = (t >> 3) & 1, e = t & 7;
            int C = p * 128 + G * 8 + (e >> 1) + (e & 1) * 4;
            int src = ((k >> 7) * 128 + (k & 127)) * 256 + C;
            v = is_sig ? ws[src] : wt[src];
        } else if (row < 768) {
            int j = row - 512;
            v = (j < 128) ? wr[k * 128 + j] : wk[k * 256 + (j - 128)];
        } else {
            v = wk[k * 256 + 128 + (row - 768)];
        }
        int q = (k & ~7) + ((k & 3) << 1) + ((k >> 2) & 1);
        wscratch[row * 256 + q] = __uint_as_float(tf32r(v));
    } else {
        size_t g = (size_t)(bid - 896) * 256 + tid;   // < 2097152 groups of 8
        const float* src = x + g * 8;
        float4 lo = *(const float4*)src;
        float4 hi = *(const float4*)(src + 4);
        lo.x = __uint_as_float(tf32r(lo.x)); lo.y = __uint_as_float(tf32r(lo.y));
        lo.z = __uint_as_float(tf32r(lo.z)); lo.w = __uint_as_float(tf32r(lo.w));
        hi.x = __uint_as_float(tf32r(hi.x)); hi.y = __uint_as_float(tf32r(hi.y));
        hi.z = __uint_as_float(tf32r(hi.z)); hi.w = __uint_as_float(tf32r(hi.w));
        float* dst = xscratch + g * 8;
        *(float4*)dst = lo;
        *(float4*)(dst + 4) = hi;
    }
}

// ------------------------------ gate kernel --------------------------------
// grid 4096: ng = bid>>10 (0..3: 128 interleaved gate rows = 64 channels),
//            mt = bid&1023 (128-token tile). 128 threads, 4 warps (2M x 2N).
__global__ void __launch_bounds__(128, 2)
gate_kernel(const float* __restrict__ bt, const float* __restrict__ bs) {
    extern __shared__ float sm[];
    uint32_t sb = smaddr(sm);
    int tid = threadIdx.x, wid = tid >> 5, lid = tid & 31;
    int r0 = lid >> 2, c0 = lid & 3;
    int rx3 = r0 & 3;
    int ng = blockIdx.x >> 10;
    int mt = blockIdx.x & 1023;
    long g0 = (long)mt * 128;
    bool head = (mt & 127) == 0;            // first tile in a batch row

    int mw = wid >> 1, nw = wid & 1;        // 2M x 2N, warp 64x64

    int mrow = ((lid >> 3) & 1) * 8 + (lid & 7);
    int gh   = lid >> 4;
    int swl  = lid & 7;

    float acc[4][8][4];
#pragma unroll
    for (int i = 0; i < 4; ++i)
#pragma unroll
        for (int j = 0; j < 8; ++j)
#pragma unroll
            for (int q = 0; q < 4; ++q) acc[i][j][q] = 0.f;

    const int ldb = tid & 7, ldrow = tid >> 3;          // ldrow 0..15
    const uint32_t ldswzA = (uint32_t)(ldb ^ (ldrow & 7));
    const uint32_t ldswzB = (uint32_t)(ldb ^ ((ldrow & 3) << 1));
    const float* wb = wscratch + ng * 32768;

    auto loadChunk = [&](int kc) {
        if (kc >= 8) return;
        int st = kc % 3;
#pragma unroll
        for (int i = 0; i < 8; ++i) {       // A: 128 rows x 32 (tap folded)
            int row = ldrow + i * 16;
            const float* srcA = xscratch;
            int sz = 16;
            if (kc < 4) {
                if (head && row < 4) sz = 0;
                else srcA = xscratch + (g0 + row - 4) * 128 + kc * 32 + ldb * 4;
            } else {
                srcA = xscratch + (g0 + row) * 128 + (kc - 4) * 32 + ldb * 4;
            }
            cpa16(sb + (uint32_t)(AOFF + st * 4096 + row * 32 + ldswzA * 4) * 4, srcA, sz);
        }
#pragma unroll
        for (int i = 0; i < 8; ++i) {       // B: 128 rows x 32
            int row = ldrow + i * 16;
            cpa16(sb + (uint32_t)(BOFF + st * 4096 + row * 32 + ldswzB * 4) * 4,
                  wb + row * 256 + kc * 32 + ldb * 4, 16);
        }
    };

    auto compute = [&](int st) {
        uint32_t Abase = sb + (uint32_t)(AOFF + st * 4096 + (mw * 64 + mrow) * 32) * 4;
        const float* Bs = sm + BOFF + st * 4096 + nw * 2048 + r0 * 32;
#pragma unroll
        for (int ks = 0; ks < 4; ++ks) {
            uint32_t xorw = (uint32_t)(((ks << 1) + gh) ^ swl) * 16;
            uint32_t a[4][4];
#pragma unroll
            for (int mf = 0; mf < 4; ++mf)
                ldsm4(a[mf], Abase + mf * 2048 + xorw);
            int o = ((ks ^ rx3) << 3) + 2 * c0;
#pragma unroll
            for (int nf = 0; nf < 8; ++nf) {
                float2 bv = *(const float2*)(Bs + nf * 256 + o);
                uint32_t b[2] = {__float_as_uint(bv.x), __float_as_uint(bv.y)};
#pragma unroll
                for (int mf = 0; mf < 4; ++mf) mma8(acc[mf][nf], a[mf], b);
            }
        }
    };

    loadChunk(0); cpcommit();
    loadChunk(1); cpcommit();
#pragma unroll 1
    for (int ci = 0; ci < 8; ++ci) {
        CPWAIT(1); __syncthreads();
        compute(ci % 3);
        loadChunk(ci + 2); cpcommit();
    }

    // epilogue: m -> gmem mscratch, PLAIN channel positions (A-side contract).
    // Thread holds channels (Cb+c0, Cb+c0+4) for token rows (tok0, tok1).
#pragma unroll
    for (int mf = 0; mf < 4; ++mf) {
        long tok0 = g0 + mw * 64 + mf * 16 + r0, tok1 = tok0 + 8;
#pragma unroll
        for (int gs = 0; gs < 4; ++gs) {
            int Gl = nw * 4 + gs;
            int Cb = ng * 64 + Gl * 8;
            float bt0 = __ldg(bt + Cb + c0), bt1 = __ldg(bt + Cb + c0 + 4);
            float bs0 = __ldg(bs + Cb + c0), bs1 = __ldg(bs + Cb + c0 + 4);
            float* At = acc[mf][2 * gs];
            float* Ag = acc[mf][2 * gs + 1];
            int Cq = Cb + c0;
            mscratch[tok0 * 256 + Cq]     = gatem(At[0] + bt0, Ag[0] + bs0);
            mscratch[tok0 * 256 + Cq + 4] = gatem(At[1] + bt1, Ag[1] + bs1);
            mscratch[tok1 * 256 + Cq]     = gatem(At[2] + bt0, Ag[2] + bs0);
            mscratch[tok1 * 256 + Cq + 4] = gatem(At[3] + bt1, Ag[3] + bs1);
        }
    }
}

// ------------------------------ out kernel ---------------------------------
// grid 3072: ng = bid>>10 (0: res, 1: skip0..127, 2: skip128..255),
//            mt = bid&1023. 128 threads, 4 warps (2M x 2N).
__global__ void __launch_bounds__(128, 2)
out_kernel(const float* __restrict__ x,
           const float* __restrict__ br, const float* __restrict__ bk,
           float* __restrict__ out) {
    extern __shared__ float sm[];
    uint32_t sb = smaddr(sm);
    int tid = threadIdx.x, wid = tid >> 5, lid = tid & 31;
    int r0 = lid >> 2, c0 = lid & 3;
    int rx3 = r0 & 3;
    int ng = blockIdx.x >> 10;
    int mt = blockIdx.x & 1023;
    long g0 = (long)mt * 128;

    int mw = wid >> 1, nw = wid & 1;        // 2M x 2N, warp 64x64

    int mrow = ((lid >> 3) & 1) * 8 + (lid & 7);
    int gh   = lid >> 4;
    int swl  = lid & 7;

    float acc[4][8][4];
#pragma unroll
    for (int i = 0; i < 4; ++i)
#pragma unroll
        for (int j = 0; j < 8; ++j)
#pragma unroll
            for (int q = 0; q < 4; ++q) acc[i][j][q] = 0.f;

    const int ldb = tid & 7, ldrow = tid >> 3;          // ldrow 0..15
    const uint32_t ldswzA = (uint32_t)(ldb ^ (ldrow & 7));
    const uint32_t ldswzB = (uint32_t)(ldb ^ ((ldrow & 3) << 1));
    const float* wb = wscratch + (size_t)(512 + ng * 128) * 256;

    auto loadChunk = [&](int kc) {
        if (kc >= 8) return;
        int st = kc % 3;
#pragma unroll
        for (int i = 0; i < 8; ++i) {       // A = m: 128 rows x 32 (plain)
            int row = ldrow + i * 16;
            cpa16(sb + (uint32_t)(AOFF + st * 4096 + row * 32 + ldswzA * 4) * 4,
                  mscratch + (g0 + row) * 256 + kc * 32 + ldb * 4, 16);
        }
#pragma unroll
        for (int i = 0; i < 8; ++i) {       // B: 128 rows x 32 (q-packed)
            int row = ldrow + i * 16;
            cpa16(sb + (uint32_t)(BOFF + st * 4096 + row * 32 + ldswzB * 4) * 4,
                  wb + row * 256 + kc * 32 + ldb * 4, 16);
        }
    };

    auto compute = [&](int st) {
        uint32_t Abase = sb + (uint32_t)(AOFF + st * 4096 + (mw * 64 + mrow) * 32) * 4;
        const float* Bs = sm + BOFF + st * 4096 + nw * 2048 + r0 * 32;
#pragma unroll
        for (int ks = 0; ks < 4; ++ks) {
            uint32_t xorw = (uint32_t)(((ks << 1) + gh) ^ swl) * 16;
            uint32_t a[4][4];
#pragma unroll
            for (int mf = 0; mf < 4; ++mf)
                ldsm4(a[mf], Abase + mf * 2048 + xorw);
            int o = ((ks ^ rx3) << 3) + 2 * c0;
#pragma unroll
            for (int nf = 0; nf < 8; ++nf) {
                float2 bv = *(const float2*)(Bs + nf * 256 + o);
                uint32_t b[2] = {__float_as_uint(bv.x), __float_as_uint(bv.y)};
#pragma unroll
                for (int mf = 0; mf < 4; ++mf) mma8(acc[mf][nf], a[mf], b);
            }
        }
    };

    loadChunk(0); cpcommit();
    loadChunk(1); cpcommit();
#pragma unroll 1
    for (int ci = 0; ci < 8; ++ci) {
        CPWAIT(1); __syncthreads();
        compute(ci % 3);
        loadChunk(ci + 2); cpcommit();
    }

    float* outR = out;                                // res  [131072,128]
    float* outK = out + (size_t)131072 * 128;         // skip [131072,256]
#pragma unroll
    for (int mf = 0; mf < 4; ++mf) {
        long row0 = g0 + mw * 64 + mf * 16 + r0, row1 = row0 + 8;
#pragma unroll
        for (int nf = 0; nf < 8; ++nf) {
            int pcolL = nw * 64 + nf * 8 + 2 * c0;
            float* A = acc[mf][nf];
            if (ng == 0) {
                float b0 = __ldg(br + pcolL), b1 = __ldg(br + pcolL + 1);
                float2 x0v = *(const float2*)(x + row0 * 128 + pcolL);
                float2 x1v = *(const float2*)(x + row1 * 128 + pcolL);
                *(float2*)(outR + row0 * 128 + pcolL) =
                    make_float2(A[0] + b0 + x0v.x, A[1] + b1 + x0v.y);
                *(float2*)(outR + row1 * 128 + pcolL) =
                    make_float2(A[2] + b0 + x1v.x, A[3] + b1 + x1v.y);
            } else {
                int ck = (ng - 1) * 128 + pcolL;
                float b0 = __ldg(bk + ck), b1 = __ldg(bk + ck + 1);
                *(float2*)(outK + row0 * 256 + ck) = make_float2(A[0] + b0, A[1] + b1);
                *(float2*)(outK + row1 * 256 + ck) = make_float2(A[2] + b0, A[3] + b1);
            }
        }
    }
}

// ------------------------------- launch ------------------------------------
extern "C" void kernel_launch(void* const* d_in, const int* in_sizes, int n_in,
                              void* d_out, int out_size) {
    const float* x  = (const float*)d_in[0];
    const float* wt = (const float*)d_in[1];
    const float* bt = (const float*)d_in[2];
    const float* ws = (const float*)d_in[3];
    const float* bs = (const float*)d_in[4];
    const float* wr = (const float*)d_in[5];
    const float* br = (const float*)d_in[6];
    const float* wk = (const float*)d_in[7];
    const float* bk = (const float*)d_in[8];
    float* out = (float*)d_out;

    cudaFuncSetAttribute(gate_kernel,
                         cudaFuncAttributeMaxDynamicSharedMemorySize, SMEM_BYTES);
    cudaFuncSetAttribute(out_kernel,
                         cudaFuncAttributeMaxDynamicSharedMemorySize, SMEM_BYTES);

    prep_kernel<<<896 + 8192, 256>>>(wt, ws, wr, wk, x);
    gate_kernel<<<4096, 128, SMEM_BYTES>>>(bt, bs);
    out_kernel<<<3072, 128, SMEM_BYTES>>>(x, br, bk, out);
}

// round 17
// speedup vs baseline: 1.3689x; 1.3689x over previous
#include <cuda_runtime.h>
#include <cuda_fp16.h>
#include <cstdint>
#include <cstddef>

// ---------------------------------------------------------------------------
// WaveNet gated residual block, fp16 mma.sync m16n8k16 (sm_103 baseline PTX).
//
// R16 = R13 two-kernel occ-2 structure with fp16 operands (same 10-bit
// mantissa as tf32; fp32 accumulation) -> 2x MACs/instruction and half the
// smem/DRAM operand traffic.
//   gate_kernel: M128 x N128 (interleaved tanh|sig rows -> 64 channels),
//                epilogue m -> gmem mscratch (plain fp16, channel pairing
//                permutation folded into the weight pack).
//   out_kernel : M128 x N128 over [res | skip0 | skip1], A = mscratch.
// Both: 8 warps, warp tile 64x32, acc 64 f32/thread, ldmatrix.x4 for BOTH
// A and B fragments (plain fp16 rows, 64B/row, XOR key (row>>1)&3 over 4
// 16B groups), 3-stage cp.async ring, one __syncthreads per k32 chunk.
// ---------------------------------------------------------------------------

#define DEVFN __device__ __forceinline__

// smem BYTE offsets (per kernel): A stages 3x8192, B stages 3x8192
static constexpr int AOFFB = 0;
static constexpr int BOFFB = 24576;
static constexpr int SMEM_BYTES = 49152;       // 2 CTAs/SM (regs-limited)

__device__ __half wscratch[896 * 256];         // packed fp16 weights (448 KB)
__device__ __half xscratch[(size_t)131072 * 128];   // fp16 x (32 MB)
__device__ __half mscratch[(size_t)131072 * 256];   // fp16 gated activations m

// ------------------------------- helpers -----------------------------------
DEVFN uint32_t smaddr(const void* p) {
    uint32_t a;
    asm("{ .reg .u64 t; cvta.to.shared.u64 t, %1; cvt.u32.u64 %0, t; }" : "=r"(a) : "l"(p));
    return a;
}
DEVFN float ex2f(float x) { float y; asm("ex2.approx.ftz.f32 %0, %1;" : "=f"(y) : "f"(x)); return y; }
DEVFN float rcpf(float x) { float y; asm("rcp.approx.ftz.f32 %0, %1;" : "=f"(y) : "f"(x)); return y; }

// tanh(a)*sigmoid(b) = (u-1)*v/((u+1)(v+1)), u=e^{2a}, v=e^{b}; clamped.
DEVFN float gatem(float a, float b) {
    a = fminf(fmaxf(a, -15.f), 15.f);
    b = fminf(fmaxf(b, -30.f), 30.f);
    float u = ex2f(a * 2.8853900817779268f);
    float v = ex2f(b * 1.4426950408889634f);
    return (u - 1.f) * v * rcpf((u + 1.f) * (v + 1.f));
}

DEVFN void cpa16(uint32_t dst, const void* src, int sz) {
    asm volatile("cp.async.cg.shared.global [%0], [%1], 16, %2;"
                 :: "r"(dst), "l"(src), "r"(sz) : "memory");
}
DEVFN void cpcommit() { asm volatile("cp.async.commit_group;" ::: "memory"); }
#define CPWAIT(n) asm volatile("cp.async.wait_group %0;" :: "n"(n) : "memory")

// m16n8k16 fp16 mma, row.col, f32 accum
DEVFN void mma16(float* d, const uint32_t* a, const uint32_t* b) {
    asm("mma.sync.aligned.m16n8k16.row.col.f32.f16.f16.f32 "
        "{%0,%1,%2,%3}, {%4,%5,%6,%7}, {%8,%9}, {%0,%1,%2,%3};"
        : "+f"(d[0]), "+f"(d[1]), "+f"(d[2]), "+f"(d[3])
        : "r"(a[0]), "r"(a[1]), "r"(a[2]), "r"(a[3]), "r"(b[0]), "r"(b[1]));
}

// ldmatrix x4 (b16): 4 independent 8x8 fp16 matrices
DEVFN void ldsm4(uint32_t* r, uint32_t addr) {
    asm volatile("ldmatrix.sync.aligned.m8n8.x4.shared.b16 {%0,%1,%2,%3}, [%4];"
                 : "=r"(r[0]), "=r"(r[1]), "=r"(r[2]), "=r"(r[3]) : "r"(addr));
}

// ------------------------------ prep kernel --------------------------------
// wscratch rows (256 plain fp16 each):
//   0..511   gate: row = p*256 + t; G=t>>4, is_sig=(t>>3)&1, e=t&7,
//            channel C = p*128 + G*8 + (e>>1) + (e&1)*4  (pairing permutation
//            so the acc fragment cols (2c0, 2c0+1) land on plain channels
//            (c0, c0+4))
//   512..767 out: res 0..127 | skip 0..127
//   768..895 out: skip 128..255
// xscratch: 128 plain fp16 per token.
__global__ void __launch_bounds__(256)
prep_kernel(const float* __restrict__ wt, const float* __restrict__ ws,
            const float* __restrict__ wr, const float* __restrict__ wk,
            const float* __restrict__ x) {
    int bid = blockIdx.x, tid = threadIdx.x;
    if (bid < 896) {
        int idx = bid * 256 + tid;
        int row = idx >> 8, k = idx & 255;
        float v;
        if (row < 512) {
            int p = row >> 8, t = row & 255;
            int G = t >> 4, is_sig = (t >> 3) & 1, e = t & 7;
            int C = p * 128 + G * 8 + (e >> 1) + (e & 1) * 4;
            int src = ((k >> 7) * 128 + (k & 127)) * 256 + C;
            v = is_sig ? ws[src] : wt[src];
        } else if (row < 768) {
            int j = row - 512;
            v = (j < 128) ? wr[k * 128 + j] : wk[k * 256 + (j - 128)];
        } else {
            v = wk[k * 256 + 128 + (row - 768)];
        }
        wscratch[row * 256 + k] = __float2half_rn(v);
    } else {
        size_t g = (size_t)(bid - 896) * 256 + tid;   // < 2097152 groups of 8
        const float* src = x + g * 8;
        float4 lo = *(const float4*)src;
        float4 hi = *(const float4*)(src + 4);
        __half h[8];
        h[0] = __float2half_rn(lo.x); h[1] = __float2half_rn(lo.y);
        h[2] = __float2half_rn(lo.z); h[3] = __float2half_rn(lo.w);
        h[4] = __float2half_rn(hi.x); h[5] = __float2half_rn(hi.y);
        h[6] = __float2half_rn(hi.z); h[7] = __float2half_rn(hi.w);
        *(uint4*)(xscratch + g * 8) = *(const uint4*)h;
    }
}

// ------------------------------ gate kernel --------------------------------
// grid 4096: ng = bid>>10 (0..3: 128 interleaved gate rows = 64 channels),
//            mt = bid&1023 (128-token tile). 256 threads, 8 warps (2M x 4N).
__global__ void __launch_bounds__(256, 2)
gate_kernel(const float* __restrict__ bt, const float* __restrict__ bs) {
    extern __shared__ char smc[];
    uint32_t sb = smaddr(smc);
    int tid = threadIdx.x, wid = tid >> 5, lid = tid & 31;
    int r0 = lid >> 2, c0 = lid & 3;
    int ng = blockIdx.x >> 10;
    int mt = blockIdx.x & 1023;
    long g0 = (long)mt * 128;
    bool head = (mt & 127) == 0;            // first tile in a batch row

    int mw = wid >> 2, nw = wid & 3;        // 2M x 4N, warp 64x32

    // ldmatrix lane constants
    int arow = (lid & 7) + ((lid >> 3) & 1) * 8;   // A: row within 16
    int agh  = lid >> 4;                            // A: 16B half of k16
    int bn_l = (lid & 7) + ((lid >> 4) << 3);       // B: n within 16
    int bkh  = (lid >> 3) & 1;                      // B: k half
    int arow_base = mw * 64 + arow;
    int akey = (arow_base >> 1) & 3;
    int bkey = (bn_l >> 1) & 3;

    float acc[4][4][4];
#pragma unroll
    for (int i = 0; i < 4; ++i)
#pragma unroll
        for (int j = 0; j < 4; ++j)
#pragma unroll
            for (int q = 0; q < 4; ++q) acc[i][j][q] = 0.f;

    const __half* wb = wscratch + (size_t)ng * 128 * 256;

    auto loadChunk = [&](int kc) {
        if (kc >= 8) return;
        int st = kc % 3;
#pragma unroll
        for (int i = 0; i < 2; ++i) {       // A: 128 rows x 32 k fp16 (tap folded)
            int idx = tid + i * 256;
            int row = idx >> 2, g = idx & 3;
            const __half* srcA = xscratch;
            int sz = 16;
            if (kc < 4) {
                if (head && row < 4) sz = 0;
                else srcA = xscratch + (g0 + row - 4) * 128 + kc * 32 + g * 8;
            } else {
                srcA = xscratch + (g0 + row) * 128 + (kc - 4) * 32 + g * 8;
            }
            cpa16(sb + (uint32_t)(AOFFB + st * 8192 + row * 64 + ((g ^ ((row >> 1) & 3)) << 4)),
                  srcA, sz);
        }
#pragma unroll
        for (int i = 0; i < 2; ++i) {       // B: 128 rows x 32 k fp16
            int idx = tid + i * 256;
            int row = idx >> 2, g = idx & 3;
            cpa16(sb + (uint32_t)(BOFFB + st * 8192 + row * 64 + ((g ^ ((row >> 1) & 3)) << 4)),
                  wb + row * 256 + kc * 32 + g * 8, 16);
        }
    };

    auto compute = [&](int st) {
        uint32_t Ab = sb + AOFFB + st * 8192;
        uint32_t Bb = sb + BOFFB + st * 8192;
#pragma unroll
        for (int ks = 0; ks < 2; ++ks) {
            uint32_t a[4][4];
#pragma unroll
            for (int mf = 0; mf < 4; ++mf)
                ldsm4(a[mf], Ab + (uint32_t)((arow_base + mf * 16) * 64
                                             + ((((ks << 1) + agh) ^ akey) << 4)));
#pragma unroll
            for (int nfp = 0; nfp < 2; ++nfp) {
                uint32_t bb[4];
                int bn = nw * 32 + nfp * 16 + bn_l;
                ldsm4(bb, Bb + (uint32_t)(bn * 64 + ((((ks << 1) + bkh) ^ bkey) << 4)));
#pragma unroll
                for (int mf = 0; mf < 4; ++mf) {
                    mma16(acc[mf][2 * nfp],     a[mf], bb);
                    mma16(acc[mf][2 * nfp + 1], a[mf], bb + 2);
                }
            }
        }
    };

    loadChunk(0); cpcommit();
    loadChunk(1); cpcommit();
#pragma unroll 1
    for (int ci = 0; ci < 8; ++ci) {
        CPWAIT(1); __syncthreads();
        compute(ci % 3);
        loadChunk(ci + 2); cpcommit();
    }

    // epilogue: m -> gmem mscratch, PLAIN channel positions.
    // Thread holds channels (Cb+c0, Cb+c0+4) for token rows (tok0, tok1).
#pragma unroll
    for (int mf = 0; mf < 4; ++mf) {
        long tok0 = g0 + mw * 64 + mf * 16 + r0, tok1 = tok0 + 8;
#pragma unroll
        for (int gs = 0; gs < 2; ++gs) {
            int Gl = nw * 2 + gs;
            int Cb = ng * 64 + Gl * 8;
            float bt0 = __ldg(bt + Cb + c0), bt1 = __ldg(bt + Cb + c0 + 4);
            float bs0 = __ldg(bs + Cb + c0), bs1 = __ldg(bs + Cb + c0 + 4);
            float* At = acc[mf][2 * gs];
            float* Ag = acc[mf][2 * gs + 1];
            int Cq = Cb + c0;
            mscratch[tok0 * 256 + Cq]     = __float2half_rn(gatem(At[0] + bt0, Ag[0] + bs0));
            mscratch[tok0 * 256 + Cq + 4] = __float2half_rn(gatem(At[1] + bt1, Ag[1] + bs1));
            mscratch[tok1 * 256 + Cq]     = __float2half_rn(gatem(At[2] + bt0, Ag[2] + bs0));
            mscratch[tok1 * 256 + Cq + 4] = __float2half_rn(gatem(At[3] + bt1, Ag[3] + bs1));
        }
    }
}

// ------------------------------ out kernel ---------------------------------
// grid 3072: ng = bid>>10 (0: res, 1: skip0..127, 2: skip128..255),
//            mt = bid&1023. 256 threads, 8 warps (2M x 4N).
__global__ void __launch_bounds__(256, 2)
out_kernel(const float* __restrict__ x,
           const float* __restrict__ br, const float* __restrict__ bk,
           float* __restrict__ out) {
    extern __shared__ char smc[];
    uint32_t sb = smaddr(smc);
    int tid = threadIdx.x, wid = tid >> 5, lid = tid & 31;
    int r0 = lid >> 2, c0 = lid & 3;
    int ng = blockIdx.x >> 10;
    int mt = blockIdx.x & 1023;
    long g0 = (long)mt * 128;

    int mw = wid >> 2, nw = wid & 3;        // 2M x 4N, warp 64x32

    int arow = (lid & 7) + ((lid >> 3) & 1) * 8;
    int agh  = lid >> 4;
    int bn_l = (lid & 7) + ((lid >> 4) << 3);
    int bkh  = (lid >> 3) & 1;
    int arow_base = mw * 64 + arow;
    int akey = (arow_base >> 1) & 3;
    int bkey = (bn_l >> 1) & 3;

    float acc[4][4][4];
#pragma unroll
    for (int i = 0; i < 4; ++i)
#pragma unroll
        for (int j = 0; j < 4; ++j)
#pragma unroll
            for (int q = 0; q < 4; ++q) acc[i][j][q] = 0.f;

    const __half* wb = wscratch + (size_t)(512 + ng * 128) * 256;

    auto loadChunk = [&](int kc) {
        if (kc >= 8) return;
        int st = kc % 3;
#pragma unroll
        for (int i = 0; i < 2; ++i) {       // A = m: 128 rows x 32 k fp16
            int idx = tid + i * 256;
            int row = idx >> 2, g = idx & 3;
            cpa16(sb + (uint32_t)(AOFFB + st * 8192 + row * 64 + ((g ^ ((row >> 1) & 3)) << 4)),
                  mscratch + (g0 + row) * 256 + kc * 32 + g * 8, 16);
        }
#pragma unroll
        for (int i = 0; i < 2; ++i) {       // B: 128 rows x 32 k fp16
            int idx = tid + i * 256;
            int row = idx >> 2, g = idx & 3;
            cpa16(sb + (uint32_t)(BOFFB + st * 8192 + row * 64 + ((g ^ ((row >> 1) & 3)) << 4)),
                  wb + row * 256 + kc * 32 + g * 8, 16);
        }
    };

    auto compute = [&](int st) {
        uint32_t Ab = sb + AOFFB + st * 8192;
        uint32_t Bb = sb + BOFFB + st * 8192;
#pragma unroll
        for (int ks = 0; ks < 2; ++ks) {
            uint32_t a[4][4];
#pragma unroll
            for (int mf = 0; mf < 4; ++mf)
                ldsm4(a[mf], Ab + (uint32_t)((arow_base + mf * 16) * 64
                                             + ((((ks << 1) + agh) ^ akey) << 4)));
#pragma unroll
            for (int nfp = 0; nfp < 2; ++nfp) {
                uint32_t bb[4];
                int bn = nw * 32 + nfp * 16 + bn_l;
                ldsm4(bb, Bb + (uint32_t)(bn * 64 + ((((ks << 1) + bkh) ^ bkey) << 4)));
#pragma unroll
                for (int mf = 0; mf < 4; ++mf) {
                    mma16(acc[mf][2 * nfp],     a[mf], bb);
                    mma16(acc[mf][2 * nfp + 1], a[mf], bb + 2);
                }
            }
        }
    };

    loadChunk(0); cpcommit();
    loadChunk(1); cpcommit();
#pragma unroll 1
    for (int ci = 0; ci < 8; ++ci) {
        CPWAIT(1); __syncthreads();
        compute(ci % 3);
        loadChunk(ci + 2); cpcommit();
    }

    float* outR = out;                                // res  [131072,128]
    float* outK = out + (size_t)131072 * 128;         // skip [131072,256]
#pragma unroll
    for (int mf = 0; mf < 4; ++mf) {
        long row0 = g0 + mw * 64 + mf * 16 + r0, row1 = row0 + 8;
#pragma unroll
        for (int nf = 0; nf < 4; ++nf) {
            int pcolL = nw * 32 + nf * 8 + 2 * c0;
            float* A = acc[mf][nf];
            if (ng == 0) {
                float b0 = __ldg(br + pcolL), b1 = __ldg(br + pcolL + 1);
                float2 x0v = *(const float2*)(x + row0 * 128 + pcolL);
                float2 x1v = *(const float2*)(x + row1 * 128 + pcolL);
                *(float2*)(outR + row0 * 128 + pcolL) =
                    make_float2(A[0] + b0 + x0v.x, A[1] + b1 + x0v.y);
                *(float2*)(outR + row1 * 128 + pcolL) =
                    make_float2(A[2] + b0 + x1v.x, A[3] + b1 + x1v.y);
            } else {
                int ck = (ng - 1) * 128 + pcolL;
                float b0 = __ldg(bk + ck), b1 = __ldg(bk + ck + 1);
                *(float2*)(outK + row0 * 256 + ck) = make_float2(A[0] + b0, A[1] + b1);
                *(float2*)(outK + row1 * 256 + ck) = make_float2(A[2] + b0, A[3] + b1);
            }
        }
    }
}

// ------------------------------- launch ------------------------------------
extern "C" void kernel_launch(void* const* d_in, const int* in_sizes, int n_in,
                              void* d_out, int out_size) {
    const float* x  = (const float*)d_in[0];
    const float* wt = (const float*)d_in[1];
    const float* bt = (const float*)d_in[2];
    const float* ws = (const float*)d_in[3];
    const float* bs = (const float*)d_in[4];
    const float* wr = (const float*)d_in[5];
    const float* br = (const float*)d_in[6];
    const float* wk = (const float*)d_in[7];
    const float* bk = (const float*)d_in[8];
    float* out = (float*)d_out;

    cudaFuncSetAttribute(gate_kernel,
                         cudaFuncAttributeMaxDynamicSharedMemorySize, SMEM_BYTES);
    cudaFuncSetAttribute(out_kernel,
                         cudaFuncAttributeMaxDynamicSharedMemorySize, SMEM_BYTES);

    prep_kernel<<<896 + 8192, 256>>>(wt, ws, wr, wk, x);
    gate_kernel<<<4096, 256, SMEM_BYTES>>>(bt, bs);
    out_kernel<<<3072, 256, SMEM_BYTES>>>(x, br, bk, out);
}